// round 15
// baseline (speedup 1.0000x reference)
#include <cuda_runtime.h>
#include <cuda_bf16.h>
#include <cstdint>

// Problem constants
#define BSZ   128
#define CDIM  2048
#define HW    196          // 14*14
#define NDESC 32
#define NANS  1845
#define CD4   (CDIM / 4)   // 512 float4 per attended row

#define TSAMP 8            // samples per chunk: one W pass for count<=8
#define ATT_BLOCKS 4096    // 128 b x 32 ctiles
#define GEMM_X 58          // ceil(1845/32)
#define CTILES 32          // attend blocks per sample

// Scratch (no allocations allowed)
__device__ float g_att[BSZ * CDIM];      // attended [B, C]
__device__ int   g_cnt[NDESC];           // samples per descriptor
__device__ int   g_list[NDESC * BSZ];    // sample ids per descriptor
__device__ int   g_done[BSZ + 1];        // per-sample tile counters; [BSZ]=grouping

// ---------------------------------------------------------------------------
// init: zero the progress counters (device globals persist across graph
// replays; determinism requires resetting them every launch).
// ---------------------------------------------------------------------------
__global__ void init_kernel() {
    int i = threadIdx.x;
    if (i <= BSZ) g_done[i] = 0;
}

// ---------------------------------------------------------------------------
// fused kernel.
// bids [0, 4096): attend — b = bid>>5, ctile = bid&31 (64 channels).
//   Publishes g_att tile, then release-increments g_done[b].
//   bid 0 additionally builds the grouping tables FIRST and bumps g_done[BSZ].
// bids [4096, 5952): gemm — d = gid&31, xt = gid>>5. Acquire-spins on the
//   grouping flag + its samples' counters, then runs the R8 GEMM
//   (TS=8 one-pass, batch-2 __ldcs W register stream).
// Work-distributor dispatches bids in order => attend occupies first; gemm
// blocks entering early spin briefly. No deadlock (attend bids all earlier).
// ---------------------------------------------------------------------------
__global__ void __launch_bounds__(256, 3)
fused_kernel(const float* __restrict__ mask,
             const float* __restrict__ feat,
             const int* __restrict__ inst32,
             const float* __restrict__ Wm,
             const float* __restrict__ bias,
             float* __restrict__ out) {
    extern __shared__ float4 dynsmem[];    // attend: smask | gemm: att tile
    const int bid = blockIdx.x;
    const int tid = threadIdx.x;
    const int warp = tid >> 5;
    const int lane = tid & 31;

    if (bid < ATT_BLOCKS) {
        // ================= attend path =================
        const int b     = bid >> 5;
        const int ctile = bid & 31;

        // ---- grouping tables first (bid 0 only) — unblocks gemm ASAP ----
        if (bid == 0) {
            __shared__ int sh_inst[BSZ];
            __shared__ int sh_flag;
            if (tid == 0) sh_flag = 0;
            __syncthreads();
            if (tid < 64) {
                // int64 little-endian => odd words of first 64 entries are 0
                if (inst32[2 * tid + 1] != 0) atomicOr(&sh_flag, 1);
            }
            __syncthreads();
            const bool is64 = (sh_flag == 0);
            if (tid < BSZ) sh_inst[tid] = is64 ? inst32[2 * tid] : inst32[tid];
            __syncthreads();
            if (tid == 0) {
                int cnt[NDESC];
                #pragma unroll
                for (int dd = 0; dd < NDESC; ++dd) cnt[dd] = 0;
                for (int bb = 0; bb < BSZ; ++bb) {
                    int dd = sh_inst[bb];
                    g_list[dd * BSZ + cnt[dd]++] = bb;
                }
                #pragma unroll
                for (int dd = 0; dd < NDESC; ++dd) g_cnt[dd] = cnt[dd];
                __threadfence();
                atomicAdd(&g_done[BSZ], 1);        // grouping ready
            }
            __syncthreads();
        }

        float4* smask = dynsmem;                   // 49 float4
        const float4* mrow =
            reinterpret_cast<const float4*>(mask + (size_t)b * HW);
        if (tid < 49) smask[tid] = mrow[tid];
        __syncthreads();

        #pragma unroll
        for (int it = 0; it < 2; ++it) {
            const int c0 = ctile * 64 + it * 32 + warp * 4;   // 4-aligned
            const float4* fr[4];
            #pragma unroll
            for (int j = 0; j < 4; ++j)
                fr[j] = reinterpret_cast<const float4*>(
                            feat + ((size_t)b * CDIM + c0 + j) * HW);

            float4 fa[4], fb[4];
            #pragma unroll
            for (int j = 0; j < 4; ++j) fa[j] = fr[j][lane];
            if (lane < 17) {
                #pragma unroll
                for (int j = 0; j < 4; ++j) fb[j] = fr[j][lane + 32];
            }

            float s[4];
            float4 ma = smask[lane];
            #pragma unroll
            for (int j = 0; j < 4; ++j)
                s[j] = fa[j].x * ma.x + fa[j].y * ma.y +
                       fa[j].z * ma.z + fa[j].w * ma.w;
            if (lane < 17) {
                float4 mb = smask[lane + 32];
                #pragma unroll
                for (int j = 0; j < 4; ++j)
                    s[j] += fb[j].x * mb.x + fb[j].y * mb.y +
                            fb[j].z * mb.z + fb[j].w * mb.w;
            }
            #pragma unroll
            for (int j = 0; j < 4; ++j)
                #pragma unroll
                for (int off = 16; off > 0; off >>= 1)
                    s[j] += __shfl_xor_sync(0xffffffffu, s[j], off);

            if (lane == 0) {
                float4 o = make_float4(s[0] * (1.0f / HW), s[1] * (1.0f / HW),
                                       s[2] * (1.0f / HW), s[3] * (1.0f / HW));
                reinterpret_cast<float4*>(g_att)[((size_t)b * CDIM + c0) >> 2] = o;
            }
        }

        // release: tile published
        __syncthreads();
        if (tid == 0) {
            __threadfence();
            atomicAdd(&g_done[b], 1);
        }
        return;
    }

    // ================= gemm path (R8) =================
    const int gid = bid - ATT_BLOCKS;
    const int d   = gid & 31;
    const int xt  = gid >> 5;                      // 0..57

    __shared__ int s_b[TSAMP];
    __shared__ int s_count;
    float4* s_att = dynsmem;                       // [TSAMP][CD4] = 64 KB

    // acquire: grouping tables ready
    if (tid == 0) {
        while (atomicAdd(&g_done[BSZ], 0) < 1) { }
        __threadfence();
        s_count = g_cnt[d];
    }
    __syncthreads();
    const int count = s_count;
    if (count == 0) return;

    const int aw = xt * 32 + warp * 4;             // first of 4 answers
    const float4* __restrict__ W4 = reinterpret_cast<const float4*>(Wm);
    unsigned wrow[4];
    #pragma unroll
    for (int ta = 0; ta < 4; ++ta) {
        int a = aw + ta; if (a >= NANS) a = NANS - 1;   // clamp; stores guarded
        wrow[ta] = (unsigned)((d * NANS + a) * CD4);
    }
    const float4* __restrict__ gatt4 = reinterpret_cast<const float4*>(g_att);

    const int nchunks = (count + TSAMP - 1) / TSAMP;   // ==1 for ~98% of d

    for (int sc = 0; sc < nchunks; ++sc) {
        if (tid < TSAMP) {
            int si = sc * TSAMP + tid;
            s_b[tid] = (si < count) ? g_list[d * BSZ + si] : -1;
        }
        __syncthreads();
        // acquire: wait for this chunk's samples to be fully attended
        if (tid == 0) {
            #pragma unroll
            for (int ts = 0; ts < TSAMP; ++ts) {
                int bb = s_b[ts];
                if (bb >= 0)
                    while (atomicAdd(&g_done[bb], 0) < CTILES) { }
            }
            __threadfence();
        }
        __syncthreads();

        // stage attended tile (full K), zeros for padding samples (L2 hits)
        for (int i = tid; i < TSAMP * CD4; i += 256) {
            int ts = i >> 9;            // / CD4
            int cc = i & (CD4 - 1);
            int bb = s_b[ts];
            float4 v = make_float4(0.f, 0.f, 0.f, 0.f);
            if (bb >= 0) v = gatt4[(size_t)bb * CD4 + cc];
            s_att[i] = v;
        }
        __syncthreads();

        float acc[4][TSAMP];
        #pragma unroll
        for (int ta = 0; ta < 4; ++ta)
            #pragma unroll
            for (int ts = 0; ts < TSAMP; ++ts) acc[ta][ts] = 0.0f;

        // K loop: 512 float4 columns / 32 lanes = 16 iters, batched by 2
        #pragma unroll
        for (int it = 0; it < CD4 / 32; it += 2) {
            const int cc0 = it * 32 + lane;
            const int cc1 = cc0 + 32;
            float4 w[2][4];
            #pragma unroll
            for (int ta = 0; ta < 4; ++ta) w[0][ta] = __ldcs(&W4[wrow[ta] + cc0]);
            #pragma unroll
            for (int ta = 0; ta < 4; ++ta) w[1][ta] = __ldcs(&W4[wrow[ta] + cc1]);

            #pragma unroll
            for (int h = 0; h < 2; ++h) {
                const int cc = it * 32 + h * 32 + lane;
                #pragma unroll
                for (int ts = 0; ts < TSAMP; ++ts) {
                    float4 av = s_att[ts * CD4 + cc];
                    #pragma unroll
                    for (int ta = 0; ta < 4; ++ta) {
                        acc[ta][ts] += w[h][ta].x * av.x;
                        acc[ta][ts] += w[h][ta].y * av.y;
                        acc[ta][ts] += w[h][ta].z * av.z;
                        acc[ta][ts] += w[h][ta].w * av.w;
                    }
                }
            }
        }

        // butterfly reduce: every lane ends with full sums
        #pragma unroll
        for (int ta = 0; ta < 4; ++ta)
            #pragma unroll
            for (int ts = 0; ts < TSAMP; ++ts)
                #pragma unroll
                for (int off = 16; off > 0; off >>= 1)
                    acc[ta][ts] += __shfl_xor_sync(0xffffffffu, acc[ta][ts], off);

        // lane l stores pair (ta = l/8, ts = l%8) — exact 32-way mapping
        {
            int ta = lane >> 3;
            int ts = lane & 7;
            int a  = aw + ta;
            int bb = s_b[ts];
            if (a < NANS && bb >= 0)
                out[(size_t)bb * NANS + a] = acc[ta][ts] + bias[(size_t)d * NANS + a];
        }
        __syncthreads();   // protect s_b / s_att before next chunk rewrites
    }
}

// ---------------------------------------------------------------------------
extern "C" void kernel_launch(void* const* d_in, const int* in_sizes, int n_in,
                              void* d_out, int out_size) {
    const float* mask = (const float*)d_in[0];   // [B,1,14,14]
    const float* feat = (const float*)d_in[1];   // [B,C,14,14]
    const int*   inst = (const int*)d_in[2];     // [B] int64 or int32
    const float* Wm   = (const float*)d_in[3];   // [32,1845,2048]
    const float* bias = (const float*)d_in[4];   // [32,1845]
    float* out = (float*)d_out;                  // [B,1845]

    static const size_t FUSED_SMEM = TSAMP * CDIM * sizeof(float);   // 64 KB
    cudaFuncSetAttribute(fused_kernel,
                         cudaFuncAttributeMaxDynamicSharedMemorySize,
                         (int)FUSED_SMEM);

    init_kernel<<<1, 256>>>();
    fused_kernel<<<ATT_BLOCKS + GEMM_X * NDESC, 256, FUSED_SMEM>>>(
        mask, feat, inst, Wm, bias, out);
}